// round 9
// baseline (speedup 1.0000x reference)
#include <cuda_runtime.h>
#include <math.h>

#define NQ 8
#define TOK_PER_BLOCK 16
#define THREADS 256          // 256 threads * 4 cols = 1024 output columns

__global__ __launch_bounds__(THREADS)
void mhaq_kernel(const float* __restrict__ x,
                 const float* __restrict__ theta,
                 const float* __restrict__ W,      // [1024, 8] row-major
                 float* __restrict__ out,
                 int n_tokens)
{
    __shared__ __align__(16) float s_W[NQ][1024];            // transposed W, 32 KB
    __shared__ __align__(16) float s_proj[TOK_PER_BLOCK][NQ];

    const int t = threadIdx.x;
    const int tokBase = blockIdx.x * TOK_PER_BLOCK;

    // ---- Phase 0: cooperative coalesced load of W, scatter transposed ----
    // 2048 float4s; thread t takes i = t, t+256, ... (consecutive lanes ->
    // consecutive 16B addresses: 4 wavefronts per warp-load).
    {
        const float4* Wv = reinterpret_cast<const float4*>(W);
        #pragma unroll
        for (int j = 0; j < 8; ++j) {
            const int i = j * THREADS + t;      // float4 index
            const float4 v = Wv[i];
            const int row = i >> 1;             // W row (output column)
            const int q0  = (i & 1) * 4;        // which half of the 8 qubits
            s_W[q0 + 0][row] = v.x;
            s_W[q0 + 1][row] = v.y;
            s_W[q0 + 2][row] = v.z;
            s_W[q0 + 3][row] = v.w;
        }
    }

    // ---- Phase 1: proj[tok][q] = cos(x[tok*1024 + q] + theta[q]) ----
    if (t < TOK_PER_BLOCK * NQ) {
        const int tok = t >> 3;
        const int q   = t & 7;
        const int gtok = tokBase + tok;
        float v = 0.0f;
        if (gtok < n_tokens) {
            v = x[(size_t)gtok * 1024 + q] + theta[q];
        }
        s_proj[tok][q] = cosf(v);
    }

    __syncthreads();

    // ---- Phase 2: register fill of this thread's W slice (conflict-free LDS.128) ----
    // wq[q] = { W[4t+0][q], W[4t+1][q], W[4t+2][q], W[4t+3][q] }
    float4 wq[NQ];
    #pragma unroll
    for (int q = 0; q < NQ; ++q) {
        wq[q] = *reinterpret_cast<const float4*>(&s_W[q][t * 4]);
    }

    // ---- Phase 3: per token: 2x broadcast LDS.128 + 32 FFMA + 1 STG.128 ----
    float* outBase = out + (size_t)tokBase * 1024 + t * 4;

    if (tokBase + TOK_PER_BLOCK <= n_tokens) {
        #pragma unroll
        for (int tok = 0; tok < TOK_PER_BLOCK; ++tok) {
            const float4 p0 = *reinterpret_cast<const float4*>(&s_proj[tok][0]);
            const float4 p1 = *reinterpret_cast<const float4*>(&s_proj[tok][4]);

            float4 o;
            o.x = p0.x * wq[0].x;  o.y = p0.x * wq[0].y;
            o.z = p0.x * wq[0].z;  o.w = p0.x * wq[0].w;

            o.x = fmaf(p0.y, wq[1].x, o.x); o.y = fmaf(p0.y, wq[1].y, o.y);
            o.z = fmaf(p0.y, wq[1].z, o.z); o.w = fmaf(p0.y, wq[1].w, o.w);
            o.x = fmaf(p0.z, wq[2].x, o.x); o.y = fmaf(p0.z, wq[2].y, o.y);
            o.z = fmaf(p0.z, wq[2].z, o.z); o.w = fmaf(p0.z, wq[2].w, o.w);
            o.x = fmaf(p0.w, wq[3].x, o.x); o.y = fmaf(p0.w, wq[3].y, o.y);
            o.z = fmaf(p0.w, wq[3].z, o.z); o.w = fmaf(p0.w, wq[3].w, o.w);

            o.x = fmaf(p1.x, wq[4].x, o.x); o.y = fmaf(p1.x, wq[4].y, o.y);
            o.z = fmaf(p1.x, wq[4].z, o.z); o.w = fmaf(p1.x, wq[4].w, o.w);
            o.x = fmaf(p1.y, wq[5].x, o.x); o.y = fmaf(p1.y, wq[5].y, o.y);
            o.z = fmaf(p1.y, wq[5].z, o.z); o.w = fmaf(p1.y, wq[5].w, o.w);
            o.x = fmaf(p1.z, wq[6].x, o.x); o.y = fmaf(p1.z, wq[6].y, o.y);
            o.z = fmaf(p1.z, wq[6].z, o.z); o.w = fmaf(p1.z, wq[6].w, o.w);
            o.x = fmaf(p1.w, wq[7].x, o.x); o.y = fmaf(p1.w, wq[7].y, o.y);
            o.z = fmaf(p1.w, wq[7].z, o.z); o.w = fmaf(p1.w, wq[7].w, o.w);

            *reinterpret_cast<float4*>(outBase + (size_t)tok * 1024) = o;
        }
    } else {
        for (int tok = 0; tok < TOK_PER_BLOCK; ++tok) {
            if (tokBase + tok >= n_tokens) break;
            const float4 p0 = *reinterpret_cast<const float4*>(&s_proj[tok][0]);
            const float4 p1 = *reinterpret_cast<const float4*>(&s_proj[tok][4]);
            float pa[NQ] = {p0.x, p0.y, p0.z, p0.w, p1.x, p1.y, p1.z, p1.w};
            float4 o = {0.f, 0.f, 0.f, 0.f};
            #pragma unroll
            for (int q = 0; q < NQ; ++q) {
                o.x = fmaf(pa[q], wq[q].x, o.x);
                o.y = fmaf(pa[q], wq[q].y, o.y);
                o.z = fmaf(pa[q], wq[q].z, o.z);
                o.w = fmaf(pa[q], wq[q].w, o.w);
            }
            *reinterpret_cast<float4*>(outBase + (size_t)tok * 1024) = o;
        }
    }
}

extern "C" void kernel_launch(void* const* d_in, const int* in_sizes, int n_in,
                              void* d_out, int out_size) {
    const float* x     = (const float*)d_in[0];   // [4,4096,1024] f32
    const float* theta = (const float*)d_in[1];   // [8] f32
    const float* W     = (const float*)d_in[2];   // [1024,8] f32
    float* out = (float*)d_out;

    const int n_tokens = in_sizes[0] / 1024;      // 16384
    const int blocks = (n_tokens + TOK_PER_BLOCK - 1) / TOK_PER_BLOCK;

    mhaq_kernel<<<blocks, THREADS>>>(x, theta, W, out, n_tokens);
}

// round 12
// speedup vs baseline: 1.0347x; 1.0347x over previous
#include <cuda_runtime.h>
#include <math.h>

#define NQ 8
#define TOK_PER_BLOCK 16
#define THREADS 256          // 256 threads * 4 cols = 1024 output columns

__global__ __launch_bounds__(THREADS)
void mhaq_kernel(const float* __restrict__ x,
                 const float* __restrict__ theta,
                 const float* __restrict__ W,      // [1024, 8] row-major
                 float* __restrict__ out,
                 int n_tokens)
{
    __shared__ __align__(16) float s_W[NQ][1024];            // transposed W, 32 KB
    __shared__ __align__(16) float s_proj[TOK_PER_BLOCK][NQ];

    const int t = threadIdx.x;
    const int tokBase = blockIdx.x * TOK_PER_BLOCK;

    // ---- Phase 0: cooperative coalesced load of W, scatter transposed ----
    // 2048 float4s; thread t takes i = t, t+256, ... (consecutive lanes ->
    // consecutive 16B addresses: 4 wavefronts per warp-load).
    {
        const float4* Wv = reinterpret_cast<const float4*>(W);
        #pragma unroll
        for (int j = 0; j < 8; ++j) {
            const int i = j * THREADS + t;      // float4 index
            const float4 v = Wv[i];
            const int row = i >> 1;             // W row (output column)
            const int q0  = (i & 1) * 4;        // which half of the 8 qubits
            s_W[q0 + 0][row] = v.x;
            s_W[q0 + 1][row] = v.y;
            s_W[q0 + 2][row] = v.z;
            s_W[q0 + 3][row] = v.w;
        }
    }

    // ---- Phase 1: proj[tok][q] = cos(x[tok*1024 + q] + theta[q]) ----
    if (t < TOK_PER_BLOCK * NQ) {
        const int tok = t >> 3;
        const int q   = t & 7;
        const int gtok = tokBase + tok;
        float v = 0.0f;
        if (gtok < n_tokens) {
            v = x[(size_t)gtok * 1024 + q] + theta[q];
        }
        s_proj[tok][q] = cosf(v);
    }

    __syncthreads();

    // ---- Phase 2: register fill of this thread's W slice (conflict-free LDS.128) ----
    // wq[q] = { W[4t+0][q], W[4t+1][q], W[4t+2][q], W[4t+3][q] }
    float4 wq[NQ];
    #pragma unroll
    for (int q = 0; q < NQ; ++q) {
        wq[q] = *reinterpret_cast<const float4*>(&s_W[q][t * 4]);
    }

    // ---- Phase 3: per token: 2x broadcast LDS.128 + 32 FFMA + 1 STG.128 ----
    float* outBase = out + (size_t)tokBase * 1024 + t * 4;

    if (tokBase + TOK_PER_BLOCK <= n_tokens) {
        #pragma unroll
        for (int tok = 0; tok < TOK_PER_BLOCK; ++tok) {
            const float4 p0 = *reinterpret_cast<const float4*>(&s_proj[tok][0]);
            const float4 p1 = *reinterpret_cast<const float4*>(&s_proj[tok][4]);

            float4 o;
            o.x = p0.x * wq[0].x;  o.y = p0.x * wq[0].y;
            o.z = p0.x * wq[0].z;  o.w = p0.x * wq[0].w;

            o.x = fmaf(p0.y, wq[1].x, o.x); o.y = fmaf(p0.y, wq[1].y, o.y);
            o.z = fmaf(p0.y, wq[1].z, o.z); o.w = fmaf(p0.y, wq[1].w, o.w);
            o.x = fmaf(p0.z, wq[2].x, o.x); o.y = fmaf(p0.z, wq[2].y, o.y);
            o.z = fmaf(p0.z, wq[2].z, o.z); o.w = fmaf(p0.z, wq[2].w, o.w);
            o.x = fmaf(p0.w, wq[3].x, o.x); o.y = fmaf(p0.w, wq[3].y, o.y);
            o.z = fmaf(p0.w, wq[3].z, o.z); o.w = fmaf(p0.w, wq[3].w, o.w);

            o.x = fmaf(p1.x, wq[4].x, o.x); o.y = fmaf(p1.x, wq[4].y, o.y);
            o.z = fmaf(p1.x, wq[4].z, o.z); o.w = fmaf(p1.x, wq[4].w, o.w);
            o.x = fmaf(p1.y, wq[5].x, o.x); o.y = fmaf(p1.y, wq[5].y, o.y);
            o.z = fmaf(p1.y, wq[5].z, o.z); o.w = fmaf(p1.y, wq[5].w, o.w);
            o.x = fmaf(p1.z, wq[6].x, o.x); o.y = fmaf(p1.z, wq[6].y, o.y);
            o.z = fmaf(p1.z, wq[6].z, o.z); o.w = fmaf(p1.z, wq[6].w, o.w);
            o.x = fmaf(p1.w, wq[7].x, o.x); o.y = fmaf(p1.w, wq[7].y, o.y);
            o.z = fmaf(p1.w, wq[7].z, o.z); o.w = fmaf(p1.w, wq[7].w, o.w);

            *reinterpret_cast<float4*>(outBase + (size_t)tok * 1024) = o;
        }
    } else {
        for (int tok = 0; tok < TOK_PER_BLOCK; ++tok) {
            if (tokBase + tok >= n_tokens) break;
            const float4 p0 = *reinterpret_cast<const float4*>(&s_proj[tok][0]);
            const float4 p1 = *reinterpret_cast<const float4*>(&s_proj[tok][4]);
            float pa[NQ] = {p0.x, p0.y, p0.z, p0.w, p1.x, p1.y, p1.z, p1.w};
            float4 o = {0.f, 0.f, 0.f, 0.f};
            #pragma unroll
            for (int q = 0; q < NQ; ++q) {
                o.x = fmaf(pa[q], wq[q].x, o.x);
                o.y = fmaf(pa[q], wq[q].y, o.y);
                o.z = fmaf(pa[q], wq[q].z, o.z);
                o.w = fmaf(pa[q], wq[q].w, o.w);
            }
            *reinterpret_cast<float4*>(outBase + (size_t)tok * 1024) = o;
        }
    }
}

extern "C" void kernel_launch(void* const* d_in, const int* in_sizes, int n_in,
                              void* d_out, int out_size) {
    const float* x     = (const float*)d_in[0];   // [4,4096,1024] f32
    const float* theta = (const float*)d_in[1];   // [8] f32
    const float* W     = (const float*)d_in[2];   // [1024,8] f32
    float* out = (float*)d_out;

    const int n_tokens = in_sizes[0] / 1024;      // 16384
    const int blocks = (n_tokens + TOK_PER_BLOCK - 1) / TOK_PER_BLOCK;

    mhaq_kernel<<<blocks, THREADS>>>(x, theta, W, out, n_tokens);
}

// round 13
// speedup vs baseline: 1.1478x; 1.1092x over previous
#include <cuda_runtime.h>
#include <math.h>

#define NQ 8
#define TOK_PER_BLOCK 16
#define THREADS 256          // 256 threads * 4 cols = 1024 output columns

__global__ __launch_bounds__(THREADS)
void mhaq_kernel(const float* __restrict__ x,
                 const float* __restrict__ theta,
                 const float* __restrict__ W,      // [1024, 8] row-major
                 float* __restrict__ out,
                 int n_tokens)
{
    __shared__ __align__(16) float s_W[NQ][1024];            // transposed W, 32 KB
    __shared__ __align__(16) float s_proj[TOK_PER_BLOCK][NQ];

    const int t = threadIdx.x;
    const int tokBase = blockIdx.x * TOK_PER_BLOCK;

    // ---- Phase 0: cooperative coalesced load of W, scatter transposed ----
    // 2048 float4s; thread t takes i = t, t+256, ... (consecutive lanes ->
    // consecutive 16B addresses: 4 wavefronts per warp-load).
    {
        const float4* Wv = reinterpret_cast<const float4*>(W);
        #pragma unroll
        for (int j = 0; j < 8; ++j) {
            const int i = j * THREADS + t;      // float4 index
            const float4 v = Wv[i];
            const int row = i >> 1;             // W row (output column)
            const int q0  = (i & 1) * 4;        // which half of the 8 qubits
            s_W[q0 + 0][row] = v.x;
            s_W[q0 + 1][row] = v.y;
            s_W[q0 + 2][row] = v.z;
            s_W[q0 + 3][row] = v.w;
        }
    }

    // ---- Phase 1: proj[tok][q] = cos(x[tok*1024 + q] + theta[q]) ----
    if (t < TOK_PER_BLOCK * NQ) {
        const int tok = t >> 3;
        const int q   = t & 7;
        const int gtok = tokBase + tok;
        float v = 0.0f;
        if (gtok < n_tokens) {
            v = x[(size_t)gtok * 1024 + q] + theta[q];
        }
        s_proj[tok][q] = cosf(v);
    }

    __syncthreads();

    // ---- Phase 2: register fill of this thread's W slice (conflict-free LDS.128) ----
    // wq[q] = { W[4t+0][q], W[4t+1][q], W[4t+2][q], W[4t+3][q] }
    float4 wq[NQ];
    #pragma unroll
    for (int q = 0; q < NQ; ++q) {
        wq[q] = *reinterpret_cast<const float4*>(&s_W[q][t * 4]);
    }

    // ---- Phase 3: per token: 2x broadcast LDS.128 + 32 FFMA + 1 STG.128 ----
    float* outBase = out + (size_t)tokBase * 1024 + t * 4;

    if (tokBase + TOK_PER_BLOCK <= n_tokens) {
        #pragma unroll
        for (int tok = 0; tok < TOK_PER_BLOCK; ++tok) {
            const float4 p0 = *reinterpret_cast<const float4*>(&s_proj[tok][0]);
            const float4 p1 = *reinterpret_cast<const float4*>(&s_proj[tok][4]);

            float4 o;
            o.x = p0.x * wq[0].x;  o.y = p0.x * wq[0].y;
            o.z = p0.x * wq[0].z;  o.w = p0.x * wq[0].w;

            o.x = fmaf(p0.y, wq[1].x, o.x); o.y = fmaf(p0.y, wq[1].y, o.y);
            o.z = fmaf(p0.y, wq[1].z, o.z); o.w = fmaf(p0.y, wq[1].w, o.w);
            o.x = fmaf(p0.z, wq[2].x, o.x); o.y = fmaf(p0.z, wq[2].y, o.y);
            o.z = fmaf(p0.z, wq[2].z, o.z); o.w = fmaf(p0.z, wq[2].w, o.w);
            o.x = fmaf(p0.w, wq[3].x, o.x); o.y = fmaf(p0.w, wq[3].y, o.y);
            o.z = fmaf(p0.w, wq[3].z, o.z); o.w = fmaf(p0.w, wq[3].w, o.w);

            o.x = fmaf(p1.x, wq[4].x, o.x); o.y = fmaf(p1.x, wq[4].y, o.y);
            o.z = fmaf(p1.x, wq[4].z, o.z); o.w = fmaf(p1.x, wq[4].w, o.w);
            o.x = fmaf(p1.y, wq[5].x, o.x); o.y = fmaf(p1.y, wq[5].y, o.y);
            o.z = fmaf(p1.y, wq[5].z, o.z); o.w = fmaf(p1.y, wq[5].w, o.w);
            o.x = fmaf(p1.z, wq[6].x, o.x); o.y = fmaf(p1.z, wq[6].y, o.y);
            o.z = fmaf(p1.z, wq[6].z, o.z); o.w = fmaf(p1.z, wq[6].w, o.w);
            o.x = fmaf(p1.w, wq[7].x, o.x); o.y = fmaf(p1.w, wq[7].y, o.y);
            o.z = fmaf(p1.w, wq[7].z, o.z); o.w = fmaf(p1.w, wq[7].w, o.w);

            *reinterpret_cast<float4*>(outBase + (size_t)tok * 1024) = o;
        }
    } else {
        for (int tok = 0; tok < TOK_PER_BLOCK; ++tok) {
            if (tokBase + tok >= n_tokens) break;
            const float4 p0 = *reinterpret_cast<const float4*>(&s_proj[tok][0]);
            const float4 p1 = *reinterpret_cast<const float4*>(&s_proj[tok][4]);
            float pa[NQ] = {p0.x, p0.y, p0.z, p0.w, p1.x, p1.y, p1.z, p1.w};
            float4 o = {0.f, 0.f, 0.f, 0.f};
            #pragma unroll
            for (int q = 0; q < NQ; ++q) {
                o.x = fmaf(pa[q], wq[q].x, o.x);
                o.y = fmaf(pa[q], wq[q].y, o.y);
                o.z = fmaf(pa[q], wq[q].z, o.z);
                o.w = fmaf(pa[q], wq[q].w, o.w);
            }
            *reinterpret_cast<float4*>(outBase + (size_t)tok * 1024) = o;
        }
    }
}

extern "C" void kernel_launch(void* const* d_in, const int* in_sizes, int n_in,
                              void* d_out, int out_size) {
    const float* x     = (const float*)d_in[0];   // [4,4096,1024] f32
    const float* theta = (const float*)d_in[1];   // [8] f32
    const float* W     = (const float*)d_in[2];   // [1024,8] f32
    float* out = (float*)d_out;

    const int n_tokens = in_sizes[0] / 1024;      // 16384
    const int blocks = (n_tokens + TOK_PER_BLOCK - 1) / TOK_PER_BLOCK;

    mhaq_kernel<<<blocks, THREADS>>>(x, theta, W, out, n_tokens);
}

// round 14
// speedup vs baseline: 1.1527x; 1.0043x over previous
#include <cuda_runtime.h>
#include <math.h>

#define NQ 8
#define TOK_PER_BLOCK 16
#define THREADS 256          // 256 threads * 4 cols = 1024 output columns

__global__ __launch_bounds__(THREADS)
void mhaq_kernel(const float* __restrict__ x,
                 const float* __restrict__ theta,
                 const float* __restrict__ W,      // [1024, 8] row-major
                 float* __restrict__ out,
                 int n_tokens)
{
    __shared__ __align__(16) float s_W[NQ][1024];            // transposed W, 32 KB
    __shared__ __align__(16) float s_proj[TOK_PER_BLOCK][NQ];

    const int t = threadIdx.x;
    const int tokBase = blockIdx.x * TOK_PER_BLOCK;

    // ---- Phase 0: cooperative coalesced load of W, scatter transposed ----
    // 2048 float4s; thread t takes i = t, t+256, ... (consecutive lanes ->
    // consecutive 16B addresses: 4 wavefronts per warp-load).
    {
        const float4* Wv = reinterpret_cast<const float4*>(W);
        #pragma unroll
        for (int j = 0; j < 8; ++j) {
            const int i = j * THREADS + t;      // float4 index
            const float4 v = Wv[i];
            const int row = i >> 1;             // W row (output column)
            const int q0  = (i & 1) * 4;        // which half of the 8 qubits
            s_W[q0 + 0][row] = v.x;
            s_W[q0 + 1][row] = v.y;
            s_W[q0 + 2][row] = v.z;
            s_W[q0 + 3][row] = v.w;
        }
    }

    // ---- Phase 1: proj[tok][q] = cos(x[tok*1024 + q] + theta[q]) ----
    if (t < TOK_PER_BLOCK * NQ) {
        const int tok = t >> 3;
        const int q   = t & 7;
        const int gtok = tokBase + tok;
        float v = 0.0f;
        if (gtok < n_tokens) {
            v = x[(size_t)gtok * 1024 + q] + theta[q];
        }
        s_proj[tok][q] = cosf(v);
    }

    __syncthreads();

    // ---- Phase 2: register fill of this thread's W slice (conflict-free LDS.128) ----
    // wq[q] = { W[4t+0][q], W[4t+1][q], W[4t+2][q], W[4t+3][q] }
    float4 wq[NQ];
    #pragma unroll
    for (int q = 0; q < NQ; ++q) {
        wq[q] = *reinterpret_cast<const float4*>(&s_W[q][t * 4]);
    }

    // ---- Phase 3: per token: 2x broadcast LDS.128 + 32 FFMA + 1 STG.128 ----
    float* outBase = out + (size_t)tokBase * 1024 + t * 4;

    if (tokBase + TOK_PER_BLOCK <= n_tokens) {
        #pragma unroll
        for (int tok = 0; tok < TOK_PER_BLOCK; ++tok) {
            const float4 p0 = *reinterpret_cast<const float4*>(&s_proj[tok][0]);
            const float4 p1 = *reinterpret_cast<const float4*>(&s_proj[tok][4]);

            float4 o;
            o.x = p0.x * wq[0].x;  o.y = p0.x * wq[0].y;
            o.z = p0.x * wq[0].z;  o.w = p0.x * wq[0].w;

            o.x = fmaf(p0.y, wq[1].x, o.x); o.y = fmaf(p0.y, wq[1].y, o.y);
            o.z = fmaf(p0.y, wq[1].z, o.z); o.w = fmaf(p0.y, wq[1].w, o.w);
            o.x = fmaf(p0.z, wq[2].x, o.x); o.y = fmaf(p0.z, wq[2].y, o.y);
            o.z = fmaf(p0.z, wq[2].z, o.z); o.w = fmaf(p0.z, wq[2].w, o.w);
            o.x = fmaf(p0.w, wq[3].x, o.x); o.y = fmaf(p0.w, wq[3].y, o.y);
            o.z = fmaf(p0.w, wq[3].z, o.z); o.w = fmaf(p0.w, wq[3].w, o.w);

            o.x = fmaf(p1.x, wq[4].x, o.x); o.y = fmaf(p1.x, wq[4].y, o.y);
            o.z = fmaf(p1.x, wq[4].z, o.z); o.w = fmaf(p1.x, wq[4].w, o.w);
            o.x = fmaf(p1.y, wq[5].x, o.x); o.y = fmaf(p1.y, wq[5].y, o.y);
            o.z = fmaf(p1.y, wq[5].z, o.z); o.w = fmaf(p1.y, wq[5].w, o.w);
            o.x = fmaf(p1.z, wq[6].x, o.x); o.y = fmaf(p1.z, wq[6].y, o.y);
            o.z = fmaf(p1.z, wq[6].z, o.z); o.w = fmaf(p1.z, wq[6].w, o.w);
            o.x = fmaf(p1.w, wq[7].x, o.x); o.y = fmaf(p1.w, wq[7].y, o.y);
            o.z = fmaf(p1.w, wq[7].z, o.z); o.w = fmaf(p1.w, wq[7].w, o.w);

            *reinterpret_cast<float4*>(outBase + (size_t)tok * 1024) = o;
        }
    } else {
        for (int tok = 0; tok < TOK_PER_BLOCK; ++tok) {
            if (tokBase + tok >= n_tokens) break;
            const float4 p0 = *reinterpret_cast<const float4*>(&s_proj[tok][0]);
            const float4 p1 = *reinterpret_cast<const float4*>(&s_proj[tok][4]);
            float pa[NQ] = {p0.x, p0.y, p0.z, p0.w, p1.x, p1.y, p1.z, p1.w};
            float4 o = {0.f, 0.f, 0.f, 0.f};
            #pragma unroll
            for (int q = 0; q < NQ; ++q) {
                o.x = fmaf(pa[q], wq[q].x, o.x);
                o.y = fmaf(pa[q], wq[q].y, o.y);
                o.z = fmaf(pa[q], wq[q].z, o.z);
                o.w = fmaf(pa[q], wq[q].w, o.w);
            }
            *reinterpret_cast<float4*>(outBase + (size_t)tok * 1024) = o;
        }
    }
}

extern "C" void kernel_launch(void* const* d_in, const int* in_sizes, int n_in,
                              void* d_out, int out_size) {
    const float* x     = (const float*)d_in[0];   // [4,4096,1024] f32
    const float* theta = (const float*)d_in[1];   // [8] f32
    const float* W     = (const float*)d_in[2];   // [1024,8] f32
    float* out = (float*)d_out;

    const int n_tokens = in_sizes[0] / 1024;      // 16384
    const int blocks = (n_tokens + TOK_PER_BLOCK - 1) / TOK_PER_BLOCK;

    mhaq_kernel<<<blocks, THREADS>>>(x, theta, W, out, n_tokens);
}